// round 2
// baseline (speedup 1.0000x reference)
#include <cuda_runtime.h>

// Problem constants
#define B_TOTAL  2
#define C_IN     32
#define HDIM     64      // H
#define WDIM     64      // W
#define J_TOTAL  4096    // H*W
#define S_TOTAL  256
#define HID      64
#define C_OUT    32
#define JPB      16      // j tiles per block
#define SCHUNK   128     // s-chunk staged in smem (32KB)

// Scratch: Q[b,s,h] = b1[h] - sx*W1[0,h] - sy*W1[1,h] + sum_c v[b,c,idx_s]*W1[2+c,h]
__device__ float g_Q[B_TOTAL * S_TOTAL * HID];

__global__ void precompute_q(const float* __restrict__ v,
                             const int* __restrict__ indices,   // int32 (JAX x64 disabled)
                             const float* __restrict__ W1,
                             const float* __restrict__ b1) {
    int s = blockIdx.x;
    int b = blockIdx.y;
    int h = threadIdx.x;              // 0..63
    int idx = indices[s] & (J_TOTAL - 1);   // defensive mask: never OOB
    int ix = idx & (WDIM - 1);
    int iy = idx >> 6;
    float sx = ix * (1.0f / 63.0f);
    float sy = iy * (1.0f / 63.0f);
    float acc = b1[h] - sx * W1[h] - sy * W1[HID + h];
    const float* vb = v + (size_t)b * C_IN * J_TOTAL + idx;
#pragma unroll
    for (int c = 0; c < C_IN; c++)
        acc = fmaf(vb[(size_t)c * J_TOTAL], W1[(2 + c) * HID + h], acc);
    g_Q[(b * S_TOTAL + s) * HID + h] = acc;
}

// Exact GELU via Abramowitz-Stegun 7.1.26 erf (max abs err ~1.5e-7).
// gelu(t) = 0.5*t*(1+erf(u)), u=t/sqrt(2).
// For u>=0: 1+erf = 2 - P(k)*exp(-u^2); for u<0: 1+erf = P(k)*exp(-u^2), k=1/(1+p|u|).
__device__ __forceinline__ float gelu_exact(float t) {
    float u  = t * 0.70710678118654752f;
    float au = fabsf(u);
    float k  = __fdividef(1.0f, fmaf(0.3275911f, au, 1.0f));   // MUFU.RCP
    float p  = fmaf(fmaf(fmaf(fmaf(1.061405429f, k, -1.453152027f),
                              k,  1.421413741f),
                         k, -0.284496736f),
                    k,  0.254829592f) * k;
    float e  = __expf(-u * u);                                  // MUFU.EX2
    float pe = p * e;
    float w  = (u >= 0.0f) ? (2.0f - pe) : pe;
    return 0.5f * t * w;
}

__global__ __launch_bounds__(256)
void nystrom_main(const float* __restrict__ W1,
                  const float* __restrict__ W2,
                  const float* __restrict__ b2,
                  float* __restrict__ out) {
    __shared__ float Qs[SCHUNK * HID];     // 32 KB; reused as Gs in epilogue
    __shared__ float W2s[HID * C_OUT];     // 8 KB
    __shared__ float w1x[HID];
    __shared__ float w1y[HID];
    __shared__ float b2s[C_OUT];

    int tid   = threadIdx.x;
    int b     = blockIdx.y;
    int j0    = blockIdx.x * JPB;
    int group = tid >> 6;                  // 0..3
    int h     = tid & 63;

    if (tid < HID) { w1x[tid] = W1[tid]; w1y[tid] = W1[HID + tid]; }
    if (tid >= 64 && tid < 64 + C_OUT) b2s[tid - 64] = b2[tid - 64];
    for (int i = tid; i < HID * C_OUT; i += 256) W2s[i] = W2[i];
    __syncthreads();

    // Each thread owns 4 j's (same h): j = j0 + group*4 + i
    float a[4], acc[4];
#pragma unroll
    for (int i = 0; i < 4; i++) {
        int j = j0 + group * 4 + i;
        float x = (j & (WDIM - 1)) * (1.0f / 63.0f);
        float y = (j >> 6)         * (1.0f / 63.0f);
        a[i] = fmaf(x, w1x[h], y * w1y[h]);
        acc[i] = 0.0f;
    }

    const float* Qg = g_Q + (size_t)b * S_TOTAL * HID;
#pragma unroll
    for (int chunk = 0; chunk < 2; chunk++) {
        __syncthreads();  // protect Qs overwrite
        for (int i = tid; i < SCHUNK * HID; i += 256)
            Qs[i] = Qg[chunk * SCHUNK * HID + i];
        __syncthreads();
#pragma unroll 4
        for (int s = 0; s < SCHUNK; s++) {
            float q = Qs[s * HID + h];
#pragma unroll
            for (int i = 0; i < 4; i++)
                acc[i] += gelu_exact(a[i] + q);
        }
    }

    // Epilogue: Gs[jj][h] = sum_s gelu; then out[b,c,j] = Gs[j]·W2[:,c]/S + b2[c]
    __syncthreads();
    float* Gs = Qs;                        // overlay (16*64 floats <= 32KB)
#pragma unroll
    for (int i = 0; i < 4; i++)
        Gs[(group * 4 + i) * HID + h] = acc[i];
    __syncthreads();

#pragma unroll
    for (int r = 0; r < 2; r++) {
        int idx = tid + r * 256;           // 512 outputs = 16 j * 32 c
        int jj  = idx >> 5;
        int c   = idx & 31;
        float sum = 0.0f;
#pragma unroll
        for (int hh = 0; hh < HID; hh++)
            sum = fmaf(Gs[jj * HID + hh], W2s[hh * C_OUT + c], sum);
        out[((size_t)b * C_OUT + c) * J_TOTAL + (j0 + jj)] =
            fmaf(sum, 1.0f / (float)S_TOTAL, b2s[c]);
    }
}

extern "C" void kernel_launch(void* const* d_in, const int* in_sizes, int n_in,
                              void* d_out, int out_size) {
    const float* v       = (const float*)d_in[0];
    const int*   indices = (const int*)d_in[1];
    const float* W1      = (const float*)d_in[2];
    const float* b1      = (const float*)d_in[3];
    const float* W2      = (const float*)d_in[4];
    const float* b2      = (const float*)d_in[5];
    float*       out     = (float*)d_out;

    precompute_q<<<dim3(S_TOTAL, B_TOTAL), HID>>>(v, indices, W1, b1);
    nystrom_main<<<dim3(J_TOTAL / JPB, B_TOTAL), 256>>>(W1, W2, b2, out);
}